// round 1
// baseline (speedup 1.0000x reference)
#include <cuda_runtime.h>

// Ultimus: x[8192,48]; QKV proj to [8192,8]; AM=softmax(Xk Xq^T / sqrt(8)) row-wise;
// Z = AM @ Xv; out = x + Z @ Zw + Zb.
// Strategy: never materialize AM. exp without max-subtraction (logits |s| <~ 8 << 88),
// so key-split partials combine additively.

#define NROWS 8192
#define DIN   48
#define DA    8
#define KSPLIT 4
#define QTILE 128
#define TK    128

// scratch (allocation-free rule: __device__ globals)
__device__ __align__(16) float g_k[NROWS * DA];   // Xk * (log2e / sqrt(8))
__device__ __align__(16) float g_q[NROWS * DA];
__device__ __align__(16) float g_v[NROWS * DA];
__device__ __align__(16) float g_acc[KSPLIT * NROWS * DA];
__device__ __align__(16) float g_sum[KSPLIT * NROWS];

__device__ __forceinline__ float ex2f(float a) {
    float r;
    asm("ex2.approx.ftz.f32 %0, %1;" : "=f"(r) : "f"(a));
    return r;
}

// ---------------- Kernel 1: QKV projections ----------------
__global__ __launch_bounds__(256) void proj_kernel(
    const float* __restrict__ x,
    const float* __restrict__ Kw, const float* __restrict__ Kb,
    const float* __restrict__ Qw, const float* __restrict__ Qb,
    const float* __restrict__ Vw, const float* __restrict__ Vb)
{
    __shared__ float sK[DIN * DA], sQ[DIN * DA], sV[DIN * DA];
    __shared__ float sKb[DA], sQb[DA], sVb[DA];
    int t = threadIdx.x;
    for (int i = t; i < DIN * DA; i += blockDim.x) { sK[i] = Kw[i]; sQ[i] = Qw[i]; sV[i] = Vw[i]; }
    if (t < DA) { sKb[t] = Kb[t]; sQb[t] = Qb[t]; sVb[t] = Vb[t]; }
    __syncthreads();

    int row = blockIdx.x * blockDim.x + t;

    float xr[DIN];
    const float4* xp = (const float4*)(x + (size_t)row * DIN);  // 192B rows -> 16B aligned
#pragma unroll
    for (int i = 0; i < DIN / 4; i++) {
        float4 v4 = xp[i];
        xr[4 * i + 0] = v4.x; xr[4 * i + 1] = v4.y; xr[4 * i + 2] = v4.z; xr[4 * i + 3] = v4.w;
    }

    float k[DA], q[DA], v[DA];
#pragma unroll
    for (int a = 0; a < DA; a++) { k[a] = sKb[a]; q[a] = sQb[a]; v[a] = sVb[a]; }
#pragma unroll
    for (int d = 0; d < DIN; d++) {
        float xd = xr[d];
#pragma unroll
        for (int a = 0; a < DA; a++) {
            k[a] = fmaf(xd, sK[d * DA + a], k[a]);
            q[a] = fmaf(xd, sQ[d * DA + a], q[a]);
            v[a] = fmaf(xd, sV[d * DA + a], v[a]);
        }
    }

    // fold (1/sqrt(8)) * log2(e) into Xk so attn inner loop is dot -> ex2
    const float SC = 1.4426950408889634f / 2.8284271247461903f;
#pragma unroll
    for (int a = 0; a < DA; a++) k[a] *= SC;

    float4* kp = (float4*)(g_k + row * DA);
    float4* qp = (float4*)(g_q + row * DA);
    float4* vp = (float4*)(g_v + row * DA);
    kp[0] = make_float4(k[0], k[1], k[2], k[3]); kp[1] = make_float4(k[4], k[5], k[6], k[7]);
    qp[0] = make_float4(q[0], q[1], q[2], q[3]); qp[1] = make_float4(q[4], q[5], q[6], q[7]);
    vp[0] = make_float4(v[0], v[1], v[2], v[3]); vp[1] = make_float4(v[4], v[5], v[6], v[7]);
}

// ---------------- Kernel 2: fused attention (partials per key-split) ----------------
__global__ __launch_bounds__(QTILE) void attn_kernel()
{
    __shared__ float4 sq[TK * 2];
    __shared__ float4 sv[TK * 2];

    int t = threadIdx.x;
    int qrow = blockIdx.x * QTILE + t;

    const float4* kp = (const float4*)(g_k + qrow * DA);
    float4 ka = kp[0];
    float4 kb = kp[1];

    float acc[DA];
#pragma unroll
    for (int a = 0; a < DA; a++) acc[a] = 0.0f;
    float ssum = 0.0f;

    int kbase = blockIdx.y * (NROWS / KSPLIT);

    for (int b = kbase; b < kbase + NROWS / KSPLIT; b += TK) {
        __syncthreads();
        const float4* gq = (const float4*)(g_q + (size_t)b * DA);
        const float4* gv = (const float4*)(g_v + (size_t)b * DA);
#pragma unroll
        for (int i = t; i < TK * 2; i += QTILE) { sq[i] = gq[i]; sv[i] = gv[i]; }
        __syncthreads();

#pragma unroll 8
        for (int j = 0; j < TK; j++) {
            float4 qa = sq[2 * j], qb = sq[2 * j + 1];
            float s;
            s = ka.x * qa.x;
            s = fmaf(ka.y, qa.y, s);
            s = fmaf(ka.z, qa.z, s);
            s = fmaf(ka.w, qa.w, s);
            s = fmaf(kb.x, qb.x, s);
            s = fmaf(kb.y, qb.y, s);
            s = fmaf(kb.z, qb.z, s);
            s = fmaf(kb.w, qb.w, s);
            float p = ex2f(s);
            ssum += p;
            float4 va = sv[2 * j], vb = sv[2 * j + 1];
            acc[0] = fmaf(p, va.x, acc[0]);
            acc[1] = fmaf(p, va.y, acc[1]);
            acc[2] = fmaf(p, va.z, acc[2]);
            acc[3] = fmaf(p, va.w, acc[3]);
            acc[4] = fmaf(p, vb.x, acc[4]);
            acc[5] = fmaf(p, vb.y, acc[5]);
            acc[6] = fmaf(p, vb.z, acc[6]);
            acc[7] = fmaf(p, vb.w, acc[7]);
        }
    }

    int o = blockIdx.y * NROWS + qrow;
    float4* ap = (float4*)(g_acc + (size_t)o * DA);
    ap[0] = make_float4(acc[0], acc[1], acc[2], acc[3]);
    ap[1] = make_float4(acc[4], acc[5], acc[6], acc[7]);
    g_sum[o] = ssum;
}

// ---------------- Kernel 3: reduce partials + normalize + output proj + residual ----------------
__global__ __launch_bounds__(256) void final_kernel(
    const float* __restrict__ x,
    const float* __restrict__ Zw, const float* __restrict__ Zb,
    float* __restrict__ out)
{
    __shared__ float sZ[DA * DIN];
    __shared__ float sZb[DIN];
    int t = threadIdx.x;
    for (int i = t; i < DA * DIN; i += blockDim.x) sZ[i] = Zw[i];
    if (t < DIN) sZb[t] = Zb[t];
    __syncthreads();

    int row = blockIdx.x * blockDim.x + t;

    float acc[DA];
#pragma unroll
    for (int a = 0; a < DA; a++) acc[a] = 0.0f;
    float ssum = 0.0f;
#pragma unroll
    for (int s = 0; s < KSPLIT; s++) {
        int o = s * NROWS + row;
        ssum += g_sum[o];
        const float4* ap = (const float4*)(g_acc + (size_t)o * DA);
        float4 a0 = ap[0], a1 = ap[1];
        acc[0] += a0.x; acc[1] += a0.y; acc[2] += a0.z; acc[3] += a0.w;
        acc[4] += a1.x; acc[5] += a1.y; acc[6] += a1.z; acc[7] += a1.w;
    }
    float inv = 1.0f / ssum;
    float z[DA];
#pragma unroll
    for (int a = 0; a < DA; a++) z[a] = acc[a] * inv;

    float o[DIN];
    const float4* xp = (const float4*)(x + (size_t)row * DIN);
#pragma unroll
    for (int i = 0; i < DIN / 4; i++) {
        float4 v4 = xp[i];
        o[4 * i + 0] = v4.x + sZb[4 * i + 0];
        o[4 * i + 1] = v4.y + sZb[4 * i + 1];
        o[4 * i + 2] = v4.z + sZb[4 * i + 2];
        o[4 * i + 3] = v4.w + sZb[4 * i + 3];
    }
#pragma unroll
    for (int a = 0; a < DA; a++) {
        float za = z[a];
#pragma unroll
        for (int c = 0; c < DIN; c++) o[c] = fmaf(za, sZ[a * DIN + c], o[c]);
    }

    float4* op = (float4*)(out + (size_t)row * DIN);
#pragma unroll
    for (int i = 0; i < DIN / 4; i++)
        op[i] = make_float4(o[4 * i + 0], o[4 * i + 1], o[4 * i + 2], o[4 * i + 3]);
}

extern "C" void kernel_launch(void* const* d_in, const int* in_sizes, int n_in,
                              void* d_out, int out_size)
{
    (void)in_sizes; (void)n_in; (void)out_size;
    const float* x  = (const float*)d_in[0];
    const float* Kw = (const float*)d_in[1];
    const float* Kb = (const float*)d_in[2];
    const float* Qw = (const float*)d_in[3];
    const float* Qb = (const float*)d_in[4];
    const float* Vw = (const float*)d_in[5];
    const float* Vb = (const float*)d_in[6];
    const float* Zw = (const float*)d_in[7];
    const float* Zb = (const float*)d_in[8];
    float* out = (float*)d_out;

    proj_kernel<<<NROWS / 256, 256>>>(x, Kw, Kb, Qw, Qb, Vw, Vb);
    dim3 g(NROWS / QTILE, KSPLIT);
    attn_kernel<<<g, QTILE>>>();
    final_kernel<<<NROWS / 256, 256>>>(x, Zw, Zb, out);
}

// round 2
// speedup vs baseline: 1.1065x; 1.1065x over previous
#include <cuda_runtime.h>

// Ultimus: x[8192,48]; QKV proj to [8192,8]; AM=softmax(Xk Xq^T / sqrt(8));
// Z = AM @ Xv; out = x + Z @ Zw + Zb.
// R2: packed f32x2 FMA in attention inner loop (2 keys/lane-pair), KSPLIT=8,
// wider grids for proj/final.

#define NROWS 8192
#define DIN   48
#define DA    8
#define KSPLIT 8
#define QTILE 128
#define TK    128

typedef unsigned long long u64;

__device__ __align__(16) float g_k[NROWS * DA];   // Xk * (log2e / sqrt(8))
__device__ __align__(16) float g_q[NROWS * DA];
__device__ __align__(16) float g_v[NROWS * DA];
__device__ __align__(16) float g_acc[KSPLIT * NROWS * DA];
__device__ __align__(16) float g_sum[KSPLIT * NROWS];

// ---- f32x2 helpers (sm_103a packed fp32; ptxas never auto-emits these) ----
__device__ __forceinline__ u64 fma2(u64 a, u64 b, u64 c) {
    u64 d; asm("fma.rn.f32x2 %0, %1, %2, %3;" : "=l"(d) : "l"(a), "l"(b), "l"(c)); return d;
}
__device__ __forceinline__ u64 mul2(u64 a, u64 b) {
    u64 d; asm("mul.rn.f32x2 %0, %1, %2;" : "=l"(d) : "l"(a), "l"(b)); return d;
}
__device__ __forceinline__ u64 add2(u64 a, u64 b) {
    u64 d; asm("add.rn.f32x2 %0, %1, %2;" : "=l"(d) : "l"(a), "l"(b)); return d;
}
__device__ __forceinline__ u64 pack2(float lo, float hi) {
    u64 d; asm("mov.b64 %0, {%1, %2};" : "=l"(d) : "f"(lo), "f"(hi)); return d;
}
__device__ __forceinline__ float2 unpack2(u64 v) {
    float2 r; asm("mov.b64 {%0, %1}, %2;" : "=f"(r.x), "=f"(r.y) : "l"(v)); return r;
}
// exp2 on both packed lanes
__device__ __forceinline__ u64 ex2_2(u64 s) {
    u64 p;
    asm("{\n\t"
        ".reg .f32 lo, hi, pl, ph;\n\t"
        "mov.b64 {lo, hi}, %1;\n\t"
        "ex2.approx.ftz.f32 pl, lo;\n\t"
        "ex2.approx.ftz.f32 ph, hi;\n\t"
        "mov.b64 %0, {pl, ph};\n\t"
        "}" : "=l"(p) : "l"(s));
    return p;
}

// ---------------- Kernel 1: QKV projections ----------------
__global__ __launch_bounds__(64) void proj_kernel(
    const float* __restrict__ x,
    const float* __restrict__ Kw, const float* __restrict__ Kb,
    const float* __restrict__ Qw, const float* __restrict__ Qb,
    const float* __restrict__ Vw, const float* __restrict__ Vb)
{
    __shared__ float sK[DIN * DA], sQ[DIN * DA], sV[DIN * DA];
    __shared__ float sKb[DA], sQb[DA], sVb[DA];
    int t = threadIdx.x;
    for (int i = t; i < DIN * DA; i += 64) { sK[i] = Kw[i]; sQ[i] = Qw[i]; sV[i] = Vw[i]; }
    if (t < DA) { sKb[t] = Kb[t]; sQb[t] = Qb[t]; sVb[t] = Vb[t]; }
    __syncthreads();

    int row = blockIdx.x * 64 + t;

    float xr[DIN];
    const float4* xp = (const float4*)(x + (size_t)row * DIN);
#pragma unroll
    for (int i = 0; i < DIN / 4; i++) {
        float4 v4 = xp[i];
        xr[4 * i + 0] = v4.x; xr[4 * i + 1] = v4.y; xr[4 * i + 2] = v4.z; xr[4 * i + 3] = v4.w;
    }

    float k[DA], q[DA], v[DA];
#pragma unroll
    for (int a = 0; a < DA; a++) { k[a] = sKb[a]; q[a] = sQb[a]; v[a] = sVb[a]; }
#pragma unroll
    for (int d = 0; d < DIN; d++) {
        float xd = xr[d];
#pragma unroll
        for (int a = 0; a < DA; a++) {
            k[a] = fmaf(xd, sK[d * DA + a], k[a]);
            q[a] = fmaf(xd, sQ[d * DA + a], q[a]);
            v[a] = fmaf(xd, sV[d * DA + a], v[a]);
        }
    }

    const float SC = 1.4426950408889634f / 2.8284271247461903f; // log2(e)/sqrt(8)
#pragma unroll
    for (int a = 0; a < DA; a++) k[a] *= SC;

    float4* kp = (float4*)(g_k + row * DA);
    float4* qp = (float4*)(g_q + row * DA);
    float4* vp = (float4*)(g_v + row * DA);
    kp[0] = make_float4(k[0], k[1], k[2], k[3]); kp[1] = make_float4(k[4], k[5], k[6], k[7]);
    qp[0] = make_float4(q[0], q[1], q[2], q[3]); qp[1] = make_float4(q[4], q[5], q[6], q[7]);
    vp[0] = make_float4(v[0], v[1], v[2], v[3]); vp[1] = make_float4(v[4], v[5], v[6], v[7]);
}

// ---------------- Kernel 2: fused attention, f32x2 packed (2 keys per pair) ----------------
__global__ __launch_bounds__(QTILE) void attn_kernel()
{
    // Transposed tiles: sqT[d][j] so an LDS.64 at even j = {q_j[d], q_{j+1}[d]}
    __shared__ float sqT[DA * TK];
    __shared__ float svT[DA * TK];

    int t = threadIdx.x;
    int qrow = blockIdx.x * QTILE + t;

    const float4* kp = (const float4*)(g_k + qrow * DA);
    float4 ka = kp[0];
    float4 kb = kp[1];
    u64 kk[DA];
    kk[0] = pack2(ka.x, ka.x); kk[1] = pack2(ka.y, ka.y);
    kk[2] = pack2(ka.z, ka.z); kk[3] = pack2(ka.w, ka.w);
    kk[4] = pack2(kb.x, kb.x); kk[5] = pack2(kb.y, kb.y);
    kk[6] = pack2(kb.z, kb.z); kk[7] = pack2(kb.w, kb.w);

    u64 acc2[DA];      // lane0 accumulates even keys, lane1 odd keys
#pragma unroll
    for (int a = 0; a < DA; a++) acc2[a] = 0ULL;
    u64 ssum2 = 0ULL;

    int kbase = blockIdx.y * (NROWS / KSPLIT);

    for (int b = kbase; b < kbase + NROWS / KSPLIT; b += TK) {
        __syncthreads();
        // thread t loads key (b+t), scatters into transposed tiles
        {
            const float4* gq = (const float4*)(g_q + (size_t)(b + t) * DA);
            const float4* gv = (const float4*)(g_v + (size_t)(b + t) * DA);
            float4 qa = gq[0], qb = gq[1];
            float4 va = gv[0], vb = gv[1];
            sqT[0 * TK + t] = qa.x; sqT[1 * TK + t] = qa.y;
            sqT[2 * TK + t] = qa.z; sqT[3 * TK + t] = qa.w;
            sqT[4 * TK + t] = qb.x; sqT[5 * TK + t] = qb.y;
            sqT[6 * TK + t] = qb.z; sqT[7 * TK + t] = qb.w;
            svT[0 * TK + t] = va.x; svT[1 * TK + t] = va.y;
            svT[2 * TK + t] = va.z; svT[3 * TK + t] = va.w;
            svT[4 * TK + t] = vb.x; svT[5 * TK + t] = vb.y;
            svT[6 * TK + t] = vb.z; svT[7 * TK + t] = vb.w;
        }
        __syncthreads();

        const u64* sq2 = (const u64*)sqT;  // [DA][TK/2] packed pairs
        const u64* sv2 = (const u64*)svT;

#pragma unroll 8
        for (int jp = 0; jp < TK / 2; jp++) {
            u64 s2 = mul2(kk[0], sq2[0 * (TK / 2) + jp]);
            s2 = fma2(kk[1], sq2[1 * (TK / 2) + jp], s2);
            s2 = fma2(kk[2], sq2[2 * (TK / 2) + jp], s2);
            s2 = fma2(kk[3], sq2[3 * (TK / 2) + jp], s2);
            s2 = fma2(kk[4], sq2[4 * (TK / 2) + jp], s2);
            s2 = fma2(kk[5], sq2[5 * (TK / 2) + jp], s2);
            s2 = fma2(kk[6], sq2[6 * (TK / 2) + jp], s2);
            s2 = fma2(kk[7], sq2[7 * (TK / 2) + jp], s2);
            u64 p2 = ex2_2(s2);
            ssum2 = add2(ssum2, p2);
#pragma unroll
            for (int a = 0; a < DA; a++)
                acc2[a] = fma2(p2, sv2[a * (TK / 2) + jp], acc2[a]);
        }
    }

    // fold the two lanes
    float acc[DA];
#pragma unroll
    for (int a = 0; a < DA; a++) {
        float2 u = unpack2(acc2[a]);
        acc[a] = u.x + u.y;
    }
    float2 su = unpack2(ssum2);
    float ssum = su.x + su.y;

    int o = blockIdx.y * NROWS + qrow;
    float4* ap = (float4*)(g_acc + (size_t)o * DA);
    ap[0] = make_float4(acc[0], acc[1], acc[2], acc[3]);
    ap[1] = make_float4(acc[4], acc[5], acc[6], acc[7]);
    g_sum[o] = ssum;
}

// ---------------- Kernel 3: reduce partials + normalize + output proj + residual ----------------
__global__ __launch_bounds__(64) void final_kernel(
    const float* __restrict__ x,
    const float* __restrict__ Zw, const float* __restrict__ Zb,
    float* __restrict__ out)
{
    __shared__ float sZ[DA * DIN];
    __shared__ float sZb[DIN];
    int t = threadIdx.x;
    for (int i = t; i < DA * DIN; i += 64) sZ[i] = Zw[i];
    if (t < DIN) sZb[t] = Zb[t];
    __syncthreads();

    int row = blockIdx.x * 64 + t;

    float acc[DA];
#pragma unroll
    for (int a = 0; a < DA; a++) acc[a] = 0.0f;
    float ssum = 0.0f;
#pragma unroll
    for (int s = 0; s < KSPLIT; s++) {
        int o = s * NROWS + row;
        ssum += g_sum[o];
        const float4* ap = (const float4*)(g_acc + (size_t)o * DA);
        float4 a0 = ap[0], a1 = ap[1];
        acc[0] += a0.x; acc[1] += a0.y; acc[2] += a0.z; acc[3] += a0.w;
        acc[4] += a1.x; acc[5] += a1.y; acc[6] += a1.z; acc[7] += a1.w;
    }
    float inv = 1.0f / ssum;
    float z[DA];
#pragma unroll
    for (int a = 0; a < DA; a++) z[a] = acc[a] * inv;

    float o[DIN];
    const float4* xp = (const float4*)(x + (size_t)row * DIN);
#pragma unroll
    for (int i = 0; i < DIN / 4; i++) {
        float4 v4 = xp[i];
        o[4 * i + 0] = v4.x + sZb[4 * i + 0];
        o[4 * i + 1] = v4.y + sZb[4 * i + 1];
        o[4 * i + 2] = v4.z + sZb[4 * i + 2];
        o[4 * i + 3] = v4.w + sZb[4 * i + 3];
    }
#pragma unroll
    for (int a = 0; a < DA; a++) {
        float za = z[a];
#pragma unroll
        for (int c = 0; c < DIN; c++) o[c] = fmaf(za, sZ[a * DIN + c], o[c]);
    }

    float4* op = (float4*)(out + (size_t)row * DIN);
#pragma unroll
    for (int i = 0; i < DIN / 4; i++)
        op[i] = make_float4(o[4 * i + 0], o[4 * i + 1], o[4 * i + 2], o[4 * i + 3]);
}

extern "C" void kernel_launch(void* const* d_in, const int* in_sizes, int n_in,
                              void* d_out, int out_size)
{
    (void)in_sizes; (void)n_in; (void)out_size;
    const float* x  = (const float*)d_in[0];
    const float* Kw = (const float*)d_in[1];
    const float* Kb = (const float*)d_in[2];
    const float* Qw = (const float*)d_in[3];
    const float* Qb = (const float*)d_in[4];
    const float* Vw = (const float*)d_in[5];
    const float* Vb = (const float*)d_in[6];
    const float* Zw = (const float*)d_in[7];
    const float* Zb = (const float*)d_in[8];
    float* out = (float*)d_out;

    proj_kernel<<<NROWS / 64, 64>>>(x, Kw, Kb, Qw, Qb, Vw, Vb);
    dim3 g(NROWS / QTILE, KSPLIT);
    attn_kernel<<<g, QTILE>>>();
    final_kernel<<<NROWS / 64, 64>>>(x, Zw, Zb, out);
}